// round 14
// baseline (speedup 1.0000x reference)
#include <cuda_runtime.h>
#include <cuda_bf16.h>
#include <cstdint>

#define B_ 256
#define N_ 512
#define M_ 1024
#define WARPS_PER_BLOCK 4
#define BLOCKS 740                    // 148 SMs * 5 CTAs, single wave

// bf16 logits table (1 MB): halves the logits L2 stream; exact bit-expand to fp32.
__device__ uint32_t g_lb[N_ * M_ / 2];

__global__ void cvt_logits_kernel(const float* __restrict__ logits) {
    int i = blockIdx.x * blockDim.x + threadIdx.x;   // pair index
    if (i < N_ * M_ / 2) {
        float2 v = ((const float2*)logits)[i];
        __nv_bfloat162 b = __float22bfloat162_rn(v); // .x -> lo, .y -> hi
        g_lb[i] = *(uint32_t*)&b;
    }
}

// FFMA-imm helpers (rt_SMSP=1). fma(a,1.0,b)==a+b, fma(a,-1.0,b)==b-a, bit-exact.
__device__ __forceinline__ float add_via_fma(float a, float b) {
    float d;
    asm("fma.rn.f32 %0, %1, 0f3F800000, %2;" : "=f"(d) : "f"(a), "f"(b));
    return d;
}
__device__ __forceinline__ float rsub_via_fma(float a, float b) {  // b - a
    float d;
    asm("fma.rn.f32 %0, %1, 0fBF800000, %2;" : "=f"(d) : "f"(a), "f"(b));
    return d;
}
__device__ __forceinline__ float fma_l2e(float a, float b) {       // a*log2e + b
    float d;
    asm("fma.rn.f32 %0, %1, 0f3FB8AA3B, %2;" : "=f"(d) : "f"(a), "f"(b));
    return d;
}

// e^(g+l) via exp2, log2e folded into range reduction, magic-round ldexp.
// Degree-3 economized poly: output rel err ~3e-5; +bf16 logit err ~6e-5.
__device__ __forceinline__ float exp_gl(float g, float l) {
    const float MAGIC = 12582912.0f;          // 2^23 + 2^22
    float z   = add_via_fma(g, l);
    float tsh = fma_l2e(z, MAGIC);
    float nrf = rsub_via_fma(tsh, MAGIC);
    float f   = fma_l2e(z, nrf);              // f in [-0.5, 0.5]
    int   bi  = __float_as_int(tsh);
    float p = fmaf(f, 0.05592078f, 0.24263103f);
    p = fmaf(f, p, 0.69312114f);
    p = fmaf(f, p, 0.99992486f);
    return __int_as_float(__float_as_int(p) + (bi << 23));
}

// Exact bf16 -> fp32: payload into the high half.
__device__ __forceinline__ float bflo(uint32_t w) { return __uint_as_float(w << 16); }
__device__ __forceinline__ float bfhi(uint32_t w) { return __uint_as_float(w & 0xFFFF0000u); }

__device__ __forceinline__ void load_row(float4 g[8], const float* __restrict__ gum,
                                         int row, int lane) {
    const float4* __restrict__ g4 = (const float4*)(gum + (size_t)row * M_) + lane;
    #pragma unroll
    for (int i = 0; i < 8; ++i) g[i] = __ldcs(&g4[i * 32]);
}

__device__ __forceinline__ void compute_row(const float4 g[8],
                                            const float4* __restrict__ xs,  // smem, +lane
                                            float* __restrict__ out,
                                            int row, int lane) {
    const int n = row & (N_ - 1);     // % N_
    const uint2* __restrict__ lb = (const uint2*)g_lb + (size_t)n * 256 + lane;

    float s = 0.0f, ws = 0.0f;
    #pragma unroll
    for (int i = 0; i < 8; ++i) {
        uint2  lw = __ldg(&lb[i * 32]);   // L2-resident bf16 table
        float4 xv = xs[i * 32];           // per-warp SMEM, own slots only

        float e0 = exp_gl(g[i].x, bflo(lw.x));
        float e1 = exp_gl(g[i].y, bfhi(lw.x));
        float e2 = exp_gl(g[i].z, bflo(lw.y));
        float e3 = exp_gl(g[i].w, bfhi(lw.y));

        s = add_via_fma(e0, s); ws = fmaf(e0, xv.x, ws);
        s = add_via_fma(e1, s); ws = fmaf(e1, xv.y, ws);
        s = add_via_fma(e2, s); ws = fmaf(e2, xv.z, ws);
        s = add_via_fma(e3, s); ws = fmaf(e3, xv.w, ws);
    }

    #pragma unroll
    for (int o = 16; o > 0; o >>= 1) {
        s  = add_via_fma(__shfl_xor_sync(0xFFFFFFFFu, s, o), s);
        ws = add_via_fma(__shfl_xor_sync(0xFFFFFFFFu, ws, o), ws);
    }
    if (lane == 0) out[row] = __fdividef(ws, s);
}

__global__ __launch_bounds__(128, 5) void gsm_kernel(
    const float* __restrict__ x,      // [B, M]
    const float* __restrict__ gum,    // [B, N, M]
    float* __restrict__ out)          // [B, N]
{
    // Per-warp x row cache: 4 warps * 1024 floats * 4B = 16 KB
    __shared__ float4 xs_s[WARPS_PER_BLOCK][M_ / 4];

    const int lane = threadIdx.x & 31;
    const int wIn  = threadIdx.x >> 5;

    // Block-contiguous range, warp-strided within the block:
    //  - the block's 4 warps read 4 consecutive rows at any instant
    //    (16 KB contiguous) -> 740 DRAM streams instead of 2960;
    //  - per-warp row counts differ by <=1 chip-wide (balanced tail).
    const int rows = B_ * N_;
    const int base = rows / BLOCKS;           // 177
    const int rem  = rows % BLOCKS;           // 92
    const int bs   = blockIdx.x * base + min((int)blockIdx.x, rem);
    const int be   = bs + base + (blockIdx.x < rem ? 1 : 0);

    float4* xs = &xs_s[wIn][lane];

    const int row0 = bs + wIn;
    if (row0 >= be) return;

    // Register double-buffer: next row's 8 LDG.128 in flight during compute.
    float4 bufA[8], bufB[8];
    load_row(bufA, gum, row0, lane);

    int bcur = -1;
    int row = row0;
    for (;;) {
        {   // A live, prefetch row+4 into B
            int nxt = row + WARPS_PER_BLOCK;
            load_row(bufB, gum, (nxt < be) ? nxt : row, lane);
            int b = row >> 9;
            if (b != bcur) {          // at most twice per block range (<512 rows)
                const float4* x4 = (const float4*)(x + (size_t)b * M_) + lane;
                #pragma unroll
                for (int i = 0; i < 8; ++i) xs[i * 32] = __ldg(&x4[i * 32]);
                bcur = b;
            }
            compute_row(bufA, xs, out, row, lane);
            row = nxt;
            if (row >= be) break;
        }
        {   // B live, prefetch row+4 into A
            int nxt = row + WARPS_PER_BLOCK;
            load_row(bufA, gum, (nxt < be) ? nxt : row, lane);
            int b = row >> 9;
            if (b != bcur) {
                const float4* x4 = (const float4*)(x + (size_t)b * M_) + lane;
                #pragma unroll
                for (int i = 0; i < 8; ++i) xs[i * 32] = __ldg(&x4[i * 32]);
                bcur = b;
            }
            compute_row(bufB, xs, out, row, lane);
            row = nxt;
            if (row >= be) break;
        }
    }
}

extern "C" void kernel_launch(void* const* d_in, const int* in_sizes, int n_in,
                              void* d_out, int out_size) {
    // Identify inputs by element count (all three distinct):
    //   input  [B, M]    = 262144
    //   logits [N, M]    = 524288
    //   gumbel [B, N, M] = 134217728
    const float* x = nullptr;
    const float* logits = nullptr;
    const float* gum = nullptr;
    for (int i = 0; i < n_in; ++i) {
        if (in_sizes[i] == B_ * M_)       x      = (const float*)d_in[i];
        else if (in_sizes[i] == N_ * M_)  logits = (const float*)d_in[i];
        else                              gum    = (const float*)d_in[i];
    }

    cvt_logits_kernel<<<(N_ * M_ / 2 + 255) / 256, 256>>>(logits);
    gsm_kernel<<<BLOCKS, 128>>>(x, gum, (float*)d_out);
}

// round 15
// speedup vs baseline: 1.0280x; 1.0280x over previous
#include <cuda_runtime.h>
#include <cuda_bf16.h>
#include <cstdint>

#define B_ 256
#define N_ 512
#define M_ 1024
#define WARPS_PER_BLOCK 4
#define BLOCKS 740                    // 148 SMs * 5 CTAs, single wave

// FFMA-imm helpers (rt_SMSP=1). fma(a,1.0,b)==a+b, fma(a,-1.0,b)==b-a, bit-exact.
__device__ __forceinline__ float add_via_fma(float a, float b) {
    float d;
    asm("fma.rn.f32 %0, %1, 0f3F800000, %2;" : "=f"(d) : "f"(a), "f"(b));
    return d;
}
__device__ __forceinline__ float rsub_via_fma(float a, float b) {  // b - a
    float d;
    asm("fma.rn.f32 %0, %1, 0fBF800000, %2;" : "=f"(d) : "f"(a), "f"(b));
    return d;
}
__device__ __forceinline__ float fma_l2e(float a, float b) {       // a*log2e + b
    float d;
    asm("fma.rn.f32 %0, %1, 0f3FB8AA3B, %2;" : "=f"(d) : "f"(a), "f"(b));
    return d;
}

// e^(g+l) via exp2, log2e folded into range reduction, magic-round ldexp:
// tsh = fma(z,L2E,MAGIC) puts round(z*log2e) in the low mantissa bits; adding
// (bits<<23) to the poly's float bits is an exact ldexp (low 9 bits of
// 0x4B400000 are zero). Degree-3 economized poly: rel err ~3e-5 (thr 1e-3).
__device__ __forceinline__ float exp_gl(float g, float l) {
    const float MAGIC = 12582912.0f;          // 2^23 + 2^22
    float z   = add_via_fma(g, l);
    float tsh = fma_l2e(z, MAGIC);
    float nrf = rsub_via_fma(tsh, MAGIC);
    float f   = fma_l2e(z, nrf);              // f in [-0.5, 0.5]
    int   bi  = __float_as_int(tsh);
    float p = fmaf(f, 0.05592078f, 0.24263103f);
    p = fmaf(f, p, 0.69312114f);
    p = fmaf(f, p, 0.99992486f);
    return __int_as_float(__float_as_int(p) + (bi << 23));
}

__device__ __forceinline__ void load_row(float4 g[8], const float* __restrict__ gum,
                                         int row, int lane) {
    const float4* __restrict__ g4 = (const float4*)(gum + (size_t)row * M_) + lane;
    #pragma unroll
    for (int i = 0; i < 8; ++i) g[i] = __ldcs(&g4[i * 32]);
}

__device__ __forceinline__ void compute_row(const float4 g[8],
                                            const float4* __restrict__ xs,  // smem, +lane
                                            const float* __restrict__ logits,
                                            float* __restrict__ out,
                                            int row, int lane) {
    const int n = row & (N_ - 1);     // % N_
    const float4* __restrict__ l4 = (const float4*)(logits + (size_t)n * M_) + lane;

    float s = 0.0f, ws = 0.0f;
    #pragma unroll
    for (int i = 0; i < 8; ++i) {
        float4 lv = __ldg(&l4[i * 32]);   // L2-resident (2 MB table)
        float4 xv = xs[i * 32];           // per-warp SMEM, own slots only

        float e0 = exp_gl(g[i].x, lv.x);
        float e1 = exp_gl(g[i].y, lv.y);
        float e2 = exp_gl(g[i].z, lv.z);
        float e3 = exp_gl(g[i].w, lv.w);

        s = add_via_fma(e0, s); ws = fmaf(e0, xv.x, ws);
        s = add_via_fma(e1, s); ws = fmaf(e1, xv.y, ws);
        s = add_via_fma(e2, s); ws = fmaf(e2, xv.z, ws);
        s = add_via_fma(e3, s); ws = fmaf(e3, xv.w, ws);
    }

    #pragma unroll
    for (int o = 16; o > 0; o >>= 1) {
        s  = add_via_fma(__shfl_xor_sync(0xFFFFFFFFu, s, o), s);
        ws = add_via_fma(__shfl_xor_sync(0xFFFFFFFFu, ws, o), ws);
    }
    if (lane == 0) out[row] = __fdividef(ws, s);
}

__global__ __launch_bounds__(128, 5) void gsm_kernel(
    const float* __restrict__ x,      // [B, M]
    const float* __restrict__ logits, // [N, M]
    const float* __restrict__ gum,    // [B, N, M]
    float* __restrict__ out)          // [B, N]
{
    // Per-warp x row cache: 4 warps * 1024 floats * 4B = 16 KB
    __shared__ float4 xs_s[WARPS_PER_BLOCK][M_ / 4];

    const int lane = threadIdx.x & 31;
    const int wIn  = threadIdx.x >> 5;

    // Block-contiguous range, warp-strided within the block:
    //  - the block's 4 warps read 4 consecutive rows at any instant
    //    (16 KB contiguous) -> 740 DRAM streams instead of 2960;
    //  - per-warp row counts differ by <=1 chip-wide (balanced tail).
    const int rows = B_ * N_;
    const int base = rows / BLOCKS;           // 177
    const int rem  = rows % BLOCKS;           // 92
    const int bs   = blockIdx.x * base + min((int)blockIdx.x, rem);
    const int be   = bs + base + (blockIdx.x < rem ? 1 : 0);

    float4* xs = &xs_s[wIn][lane];

    const int row0 = bs + wIn;
    if (row0 >= be) return;

    // Register double-buffer: next row's 8 LDG.128 in flight during compute.
    float4 bufA[8], bufB[8];
    load_row(bufA, gum, row0, lane);

    int bcur = -1;
    int row = row0;
    for (;;) {
        {   // A live, prefetch row+4 into B
            int nxt = row + WARPS_PER_BLOCK;
            load_row(bufB, gum, (nxt < be) ? nxt : row, lane);
            int b = row >> 9;
            if (b != bcur) {          // at most twice per block range (<512 rows)
                const float4* x4 = (const float4*)(x + (size_t)b * M_) + lane;
                #pragma unroll
                for (int i = 0; i < 8; ++i) xs[i * 32] = __ldg(&x4[i * 32]);
                bcur = b;
            }
            compute_row(bufA, xs, logits, out, row, lane);
            row = nxt;
            if (row >= be) break;
        }
        {   // B live, prefetch row+4 into A
            int nxt = row + WARPS_PER_BLOCK;
            load_row(bufA, gum, (nxt < be) ? nxt : row, lane);
            int b = row >> 9;
            if (b != bcur) {
                const float4* x4 = (const float4*)(x + (size_t)b * M_) + lane;
                #pragma unroll
                for (int i = 0; i < 8; ++i) xs[i * 32] = __ldg(&x4[i * 32]);
                bcur = b;
            }
            compute_row(bufB, xs, logits, out, row, lane);
            row = nxt;
            if (row >= be) break;
        }
    }
}

extern "C" void kernel_launch(void* const* d_in, const int* in_sizes, int n_in,
                              void* d_out, int out_size) {
    // Identify inputs by element count (all three distinct):
    //   input  [B, M]    = 262144
    //   logits [N, M]    = 524288
    //   gumbel [B, N, M] = 134217728
    const float* x = nullptr;
    const float* logits = nullptr;
    const float* gum = nullptr;
    for (int i = 0; i < n_in; ++i) {
        if (in_sizes[i] == B_ * M_)       x      = (const float*)d_in[i];
        else if (in_sizes[i] == N_ * M_)  logits = (const float*)d_in[i];
        else                              gum    = (const float*)d_in[i];
    }

    // Single launch: no preamble kernel.
    gsm_kernel<<<BLOCKS, 128>>>(x, logits, gum, (float*)d_out);
}